// round 3
// baseline (speedup 1.0000x reference)
#include <cuda_runtime.h>
#include <stdint.h>
#include <math_constants.h>

#define K_CODES 8192
#define DIM     256
#define NTOK    32768
#define HW      1024

#define BM 128
#define BN 128
#define BK 16

// output layout (floats): loss | quantized | indices | new_count | new_weight | new_codebook
#define OUT_LOSS 0
#define OUT_Q    1
#define OUT_IDX  (OUT_Q  + 32*DIM*HW)
#define OUT_CNT  (OUT_IDX + NTOK)
#define OUT_W    (OUT_CNT + K_CODES)
#define OUT_CB   (OUT_W   + K_CODES*DIM)

// device scratch (no allocations allowed)
__device__ float              g_cbnorm[K_CODES];
__device__ float              g_znorm[NTOK];
__device__ unsigned long long g_best[NTOK];
__device__ float              g_counts[K_CODES];
__device__ float              g_dw[K_CODES * DIM];
__device__ double             g_loss;
__device__ int                g_idx[NTOK];

// ---------------- init ----------------
__global__ void init_kernel() {
    int i = blockIdx.x * blockDim.x + threadIdx.x;
    if (i < K_CODES * DIM) g_dw[i] = 0.0f;
    if (i < NTOK)          g_best[i] = 0xFFFFFFFFFFFFFFFFull;
    if (i < K_CODES)       g_counts[i] = 0.0f;
    if (i == 0)            g_loss = 0.0;
}

// ---------------- token norms ||z||^2 (fp64 accumulate -> fp32) ----------------
__global__ void znorm_kernel(const float* __restrict__ x) {
    int token = blockIdx.x * blockDim.x + threadIdx.x;
    int b = token >> 10, hw = token & 1023;
    const float* p = x + (size_t)b * DIM * HW + hw;
    double s = 0.0;
    #pragma unroll 8
    for (int d = 0; d < DIM; d++) {
        double v = (double)p[(size_t)d * HW];
        s = fma(v, v, s);
    }
    g_znorm[token] = (float)s;
}

// ---------------- codebook row norms (fp64 -> fp32) ----------------
__global__ void cbnorm_kernel(const float* __restrict__ cb) {
    int gt   = blockIdx.x * blockDim.x + threadIdx.x;
    int code = gt >> 5;
    int lane = gt & 31;
    if (code >= K_CODES) return;
    const float* r = cb + (size_t)code * DIM;
    double s = 0.0;
    #pragma unroll
    for (int i = lane; i < DIM; i += 32) {
        double v = (double)__ldg(r + i);
        s = fma(v, v, s);
    }
    #pragma unroll
    for (int o = 16; o; o >>= 1)
        s += __shfl_down_sync(0xFFFFFFFFu, s, o);
    if (lane == 0) g_cbnorm[code] = (float)s;
}

// ---------------- fused distance GEMM (packed f32x2 FFMA2) + argmin ----------------
__global__ void __launch_bounds__(256, 2)
gemm_argmin(const float* __restrict__ x, const float* __restrict__ cb) {
    __shared__ float As[BK][BM];
    __shared__ float Bs[BK][BN + 4];

    const int tb  = blockIdx.y;           // token tile (256 tiles)
    const int cbk = blockIdx.x;           // code tile (64 tiles)
    const int b   = (tb * BM) >> 10;
    const int hw0 = (tb * BM) & 1023;
    const float* xbase  = x  + (size_t)b * DIM * HW + hw0;
    const float* cbbase = cb + (size_t)cbk * BN * DIM;

    const int tid = threadIdx.x;

    // 8 tokens x 8 codes per thread; codes packed in pairs -> 8x4 f32x2 accumulators
    unsigned long long acc2[8][4];
    #pragma unroll
    for (int i = 0; i < 8; i++)
        #pragma unroll
        for (int p = 0; p < 4; p++) acc2[i][p] = 0ull;

    const int trow = (tid >> 4) * 8;   // token sub-tile
    const int tcol = (tid & 15) * 8;   // code sub-tile

    for (int k0 = 0; k0 < DIM; k0 += BK) {
        // A tile: 16 d-rows x 128 tokens, coalesced float4 loads
        {
            int d  = tid >> 4;            // 0..15
            int t4 = (tid & 15) * 8;      // 0..120
            const float4* src = (const float4*)(xbase + (size_t)(k0 + d) * HW + t4);
            float4 v0 = src[0];
            float4 v1 = src[1];
            *(float4*)&As[d][t4]     = v0;
            *(float4*)&As[d][t4 + 4] = v1;
        }
        // B tile: 128 codes x 16 d, transpose into Bs[d][code]
        {
            int cc = tid >> 1;            // 0..127
            int dp = (tid & 1) * 8;       // 0 or 8
            const float4* src = (const float4*)(cbbase + (size_t)cc * DIM + k0 + dp);
            float4 v0 = src[0];
            float4 v1 = src[1];
            Bs[dp + 0][cc] = v0.x; Bs[dp + 1][cc] = v0.y;
            Bs[dp + 2][cc] = v0.z; Bs[dp + 3][cc] = v0.w;
            Bs[dp + 4][cc] = v1.x; Bs[dp + 5][cc] = v1.y;
            Bs[dp + 6][cc] = v1.z; Bs[dp + 7][cc] = v1.w;
        }
        __syncthreads();

        #pragma unroll
        for (int kk = 0; kk < BK; kk++) {
            float a[8];
            *(float4*)&a[0] = *(float4*)&As[kk][trow];
            *(float4*)&a[4] = *(float4*)&As[kk][trow + 4];
            // b pairs: 8 consecutive codes = 4 x f32x2 (64-bit lanes, 16B aligned)
            unsigned long long b2[4];
            {
                const ulonglong2* bp = (const ulonglong2*)&Bs[kk][tcol];
                ulonglong2 q0 = bp[0];
                ulonglong2 q1 = bp[1];
                b2[0] = q0.x; b2[1] = q0.y; b2[2] = q1.x; b2[3] = q1.y;
            }
            #pragma unroll
            for (int i = 0; i < 8; i++) {
                unsigned long long a2;
                asm("mov.b64 %0, {%1, %1};" : "=l"(a2) : "r"(__float_as_uint(a[i])));
                #pragma unroll
                for (int p = 0; p < 4; p++) {
                    asm("fma.rn.f32x2 %0, %1, %2, %0;"
                        : "+l"(acc2[i][p]) : "l"(a2), "l"(b2[p]));
                }
            }
        }
        __syncthreads();
    }

    // epilogue replicating reference fp32 rounding:
    //   d = fl( fl(znorm + cnorm) - 2*dot ), lexicographic (d, idx) min.
    const int token0 = tb * BM + trow;
    const int code0  = cbk * BN + tcol;
    float cn[8];
    #pragma unroll
    for (int j = 0; j < 8; j++) cn[j] = g_cbnorm[code0 + j];

    #pragma unroll
    for (int i = 0; i < 8; i++) {
        float zn = g_znorm[token0 + i];
        unsigned long long bestpk = 0xFFFFFFFFFFFFFFFFull;
        #pragma unroll
        for (int p = 0; p < 4; p++) {
            unsigned long long v = acc2[i][p];
            float dot_lo = __uint_as_float((unsigned int)(v & 0xFFFFFFFFull));
            float dot_hi = __uint_as_float((unsigned int)(v >> 32));
            #pragma unroll
            for (int h = 0; h < 2; h++) {          // ascending code index order
                int   j   = 2 * p + h;
                float dot = h ? dot_hi : dot_lo;
                float t1  = __fadd_rn(zn, cn[j]);
                float d   = __fsub_rn(t1, __fmul_rn(2.0f, dot));
                unsigned int e = __float_as_uint(d);
                e = (e & 0x80000000u) ? ~e : (e | 0x80000000u);
                unsigned long long pk =
                    ((unsigned long long)e << 32) | (unsigned int)(code0 + j);
                if (pk < bestpk) bestpk = pk;
            }
        }
        atomicMin(&g_best[token0 + i], bestpk);
    }
}

// ---------------- extract indices, bump counts ----------------
__global__ void post_idx(float* __restrict__ out) {
    int n = blockIdx.x * blockDim.x + threadIdx.x;
    if (n >= NTOK) return;
    unsigned long long pk = g_best[n];
    int id = (int)(pk & 0xFFFFFFFFull);
    g_idx[n] = id;
    out[OUT_IDX + n] = (float)id;
    atomicAdd(&g_counts[id], 1.0f);
}

// ---------------- quantized output + commitment loss ----------------
__global__ void quant_loss(const float* __restrict__ x,
                           const float* __restrict__ cb,
                           float* __restrict__ out) {
    __shared__ float sred[256];
    int n = blockIdx.x;
    int c = threadIdx.x;
    int id = g_idx[n];
    float q = __ldg(cb + (size_t)id * DIM + c);
    int b = n >> 10, hw = n & 1023;
    size_t off = (size_t)b * DIM * HW + (size_t)c * HW + hw;
    float xv = x[off];
    out[OUT_Q + off] = __fadd_rn(xv, __fsub_rn(q, xv));  // straight-through, fp32 like jax
    float d = __fsub_rn(q, xv);
    sred[c] = d * d;
    __syncthreads();
    #pragma unroll
    for (int s = 128; s > 0; s >>= 1) {
        if (c < s) sred[c] += sred[c + s];
        __syncthreads();
    }
    if (c == 0) atomicAdd(&g_loss, (double)sred[0]);
}

// ---------------- dw = segment_sum(flat, idx) ----------------
__global__ void dw_kernel(const float* __restrict__ x) {
    int n = blockIdx.x * blockDim.x + threadIdx.x;
    int d = blockIdx.y;
    int b = n >> 10, hw = n & 1023;
    float v = x[(size_t)b * DIM * HW + (size_t)d * HW + hw];
    atomicAdd(&g_dw[(size_t)g_idx[n] * DIM + d], v);
}

// ---------------- EMA finalize ----------------
__global__ void final_kernel(const float* __restrict__ ema_count,
                             const float* __restrict__ ema_weight,
                             float* __restrict__ out) {
    int k = blockIdx.x;
    int c = threadIdx.x;
    float nc = ema_count[k] * 0.95f + 0.05f * g_counts[k];
    const float denom = (float)(32768.0 + 8192.0 * 1e-5);  // n + K*EPS
    nc = (nc + 1e-5f) / denom * 32768.0f;
    float w = ema_weight[(size_t)k * DIM + c] * 0.95f + 0.05f * g_dw[(size_t)k * DIM + c];
    out[OUT_W  + (size_t)k * DIM + c] = w;
    out[OUT_CB + (size_t)k * DIM + c] = w / nc;
    if (c == 0) out[OUT_CNT + k] = nc;
    if (k == 0 && c == 0) {
        double mean = g_loss / (double)((size_t)NTOK * DIM);
        out[OUT_LOSS] = 0.25f * (float)mean;
    }
}

extern "C" void kernel_launch(void* const* d_in, const int* in_sizes, int n_in,
                              void* d_out, int out_size) {
    const float* x          = (const float*)d_in[0];
    const float* cb         = (const float*)d_in[1];
    const float* ema_count  = (const float*)d_in[2];
    const float* ema_weight = (const float*)d_in[3];
    float* out = (float*)d_out;

    init_kernel<<<(K_CODES * DIM + 255) / 256, 256>>>();
    znorm_kernel<<<NTOK / 256, 256>>>(x);
    cbnorm_kernel<<<(K_CODES * 32 + 255) / 256, 256>>>(cb);
    gemm_argmin<<<dim3(K_CODES / BN, NTOK / BM), 256>>>(x, cb);
    post_idx<<<NTOK / 256, 256>>>(out);
    quant_loss<<<NTOK, 256>>>(x, cb, out);
    dw_kernel<<<dim3(NTOK / 256, DIM), 256>>>(x);
    final_kernel<<<K_CODES, DIM>>>(ema_count, ema_weight, out);
}

// round 6
// speedup vs baseline: 1.8165x; 1.8165x over previous
#include <cuda_runtime.h>
#include <stdint.h>
#include <math_constants.h>

#define K_CODES 8192
#define DIM     256
#define NTOK    32768
#define HW      1024

// output layout (floats): loss | quantized | indices | new_count | new_weight | new_codebook
#define OUT_LOSS 0
#define OUT_Q    1
#define OUT_IDX  (OUT_Q  + 32*DIM*HW)
#define OUT_CNT  (OUT_IDX + NTOK)
#define OUT_W    (OUT_CNT + K_CODES)
#define OUT_CB   (OUT_W   + K_CODES*DIM)

// ---------------- device scratch ----------------
__device__ __align__(128) float g_xhi[NTOK * DIM];      // x layout: [b][d][hw]
__device__ __align__(128) float g_xlo[NTOK * DIM];
__device__ __align__(128) float g_cbhiT[DIM * K_CODES]; // transposed: [d][code]
__device__ __align__(128) float g_cbloT[DIM * K_CODES];
__device__ float              g_cbnorm[K_CODES];
__device__ float              g_znorm[NTOK];
__device__ unsigned long long g_best[NTOK];
__device__ float              g_counts[K_CODES];
__device__ float              g_dw[K_CODES * DIM];
__device__ double             g_loss;
__device__ int                g_idx[NTOK];

__device__ __forceinline__ uint32_t smem_u32(const void* p) {
    uint32_t a;
    asm("{ .reg .u64 t; cvta.to.shared.u64 t, %1; cvt.u32.u64 %0, t; }" : "=r"(a) : "l"(p));
    return a;
}
__device__ __forceinline__ float to_tf32(float v) {
    uint32_t u;
    asm("cvt.rna.satfinite.tf32.f32 %0, %1;" : "=r"(u) : "f"(v));
    return __uint_as_float(u);
}
#define CP16(dst, src) \
    asm volatile("cp.async.ca.shared.global [%0], [%1], 16;" :: "r"(dst), "l"(src))
#define CP_COMMIT() asm volatile("cp.async.commit_group;" ::: "memory")
#define CP_WAIT1()  asm volatile("cp.async.wait_group 1;" ::: "memory")
#define CP_WAIT0()  asm volatile("cp.async.wait_group 0;" ::: "memory")

#define MMA_TF32(c, a, b) \
    asm volatile("mma.sync.aligned.m16n8k8.row.col.f32.tf32.tf32.f32 " \
        "{%0,%1,%2,%3}, {%4,%5,%6,%7}, {%8,%9}, {%0,%1,%2,%3};" \
        : "+f"((c)[0]), "+f"((c)[1]), "+f"((c)[2]), "+f"((c)[3]) \
        : "r"((a)[0]), "r"((a)[1]), "r"((a)[2]), "r"((a)[3]), "r"((b)[0]), "r"((b)[1]))

// ---------------- init ----------------
__global__ void init_kernel() {
    int i = blockIdx.x * blockDim.x + threadIdx.x;
    if (i < K_CODES * DIM) g_dw[i] = 0.0f;
    if (i < NTOK)          g_best[i] = 0xFFFFFFFFFFFFFFFFull;
    if (i < K_CODES)       g_counts[i] = 0.0f;
    if (i == 0)            g_loss = 0.0;
}

// ---------------- decompose x -> tf32 hi/lo (same layout) ----------------
__global__ void decomp_x(const float* __restrict__ x) {
    int i = blockIdx.x * blockDim.x + threadIdx.x;
    float v  = x[i];
    float hi = to_tf32(v);
    g_xhi[i] = hi;
    g_xlo[i] = to_tf32(v - hi);
}

// ---------------- decompose + transpose codebook -> [d][code] hi/lo ----------------
__global__ void decomp_cbT(const float* __restrict__ cb) {
    __shared__ float tile[32][33];
    int tx = threadIdx.x, ty = threadIdx.y;
    int c0 = blockIdx.x * 32, d0 = blockIdx.y * 32;
    tile[ty][tx] = cb[(size_t)(c0 + ty) * DIM + d0 + tx];
    __syncthreads();
    float v  = tile[tx][ty];                  // code = c0+tx, d = d0+ty
    float hi = to_tf32(v);
    size_t o = (size_t)(d0 + ty) * K_CODES + c0 + tx;
    g_cbhiT[o] = hi;
    g_cbloT[o] = to_tf32(v - hi);
}

// ---------------- token norms (fp64 -> fp32) ----------------
__global__ void znorm_kernel(const float* __restrict__ x) {
    int token = blockIdx.x * blockDim.x + threadIdx.x;
    int b = token >> 10, hw = token & 1023;
    const float* p = x + (size_t)b * DIM * HW + hw;
    double s = 0.0;
    #pragma unroll 8
    for (int d = 0; d < DIM; d++) {
        double v = (double)p[(size_t)d * HW];
        s = fma(v, v, s);
    }
    g_znorm[token] = (float)s;
}

// ---------------- codebook norms (fp64 -> fp32) ----------------
__global__ void cbnorm_kernel(const float* __restrict__ cb) {
    int gt = blockIdx.x * blockDim.x + threadIdx.x;
    int code = gt >> 5, lane = gt & 31;
    if (code >= K_CODES) return;
    const float* r = cb + (size_t)code * DIM;
    double s = 0.0;
    #pragma unroll
    for (int i = lane; i < DIM; i += 32) {
        double v = (double)__ldg(r + i);
        s = fma(v, v, s);
    }
    #pragma unroll
    for (int o = 16; o; o >>= 1) s += __shfl_down_sync(0xFFFFFFFFu, s, o);
    if (lane == 0) g_cbnorm[code] = (float)s;
}

// ---------------- 3xTF32 mma.sync distance GEMM + argmin ----------------
// grid (64, 256): 128 codes x 128 tokens per CTA; BK=32, 2-stage cp.async.
// smem per stage: Ahi | Alo | Bhi | Blo, each 32 rows x 136 floats (pad 8).
#define ROWP    136
#define ARR_F   (32 * ROWP)          // 4352 floats per array
#define STAGE_F (4 * ARR_F)          // 17408 floats per stage
#define SMEM_B  (2 * STAGE_F * 4)    // 139264 bytes

__global__ void __launch_bounds__(256, 1)
gemm_argmin_tc(void) {
    extern __shared__ float smf[];
    const uint32_t smb = smem_u32(smf);

    const int tid  = threadIdx.x;
    const int lane = tid & 31;
    const int wid  = tid >> 5;
    const int g    = lane >> 2;        // 0..7
    const int q    = lane & 3;         // 0..3

    const int tb  = blockIdx.y;                   // token tile
    const int ct  = blockIdx.x;                   // code tile
    const int b   = (tb * 128) >> 10;
    const int hw0 = (tb * 128) & 1023;
    const int nt0 = ct * 128;

    const int mbase = (wid & 3) * 32;   // warp token offset
    const int nbase = (wid >> 2) * 64;  // warp code offset

    float acc[2][8][4];
    #pragma unroll
    for (int mf = 0; mf < 2; mf++)
        #pragma unroll
        for (int nf = 0; nf < 8; nf++)
            #pragma unroll
            for (int c = 0; c < 4; c++) acc[mf][nf][c] = 0.0f;

    // stage issue: each array tile = 32 rows x 128 floats = 1024 float4;
    // 256 threads x 4 float4 per array. smem row pitch ROWP=136 floats.
    auto issue = [&](int s, int k0) {
        const float* srcA[2] = {
            g_xhi + ((size_t)(b * DIM + k0) << 10) + hw0,
            g_xlo + ((size_t)(b * DIM + k0) << 10) + hw0 };
        const float* srcB[2] = {
            g_cbhiT + ((size_t)k0 << 13) + nt0,
            g_cbloT + ((size_t)k0 << 13) + nt0 };
        #pragma unroll
        for (int arr = 0; arr < 4; arr++) {
            const float* bp = (arr < 2) ? srcA[arr] : srcB[arr - 2];
            const size_t rstride = (arr < 2) ? 1024 : 8192;  // gmem row stride (floats)
            #pragma unroll
            for (int i = 0; i < 4; i++) {
                int idx = i * 256 + tid;         // 0..1023
                int row = idx >> 5;              // 0..31
                int seg = (idx & 31) * 4;        // 0..124
                uint32_t dst = smb + 4u * (s * STAGE_F + arr * ARR_F + row * ROWP + seg);
                CP16(dst, bp + (size_t)row * rstride + seg);
            }
        }
        CP_COMMIT();
    };

    issue(0, 0);

    #pragma unroll 1
    for (int ks = 0; ks < 8; ks++) {
        if (ks < 7) issue((ks + 1) & 1, (ks + 1) * 32);
        if (ks < 7) CP_WAIT1(); else CP_WAIT0();
        __syncthreads();

        const uint32_t* Ah = (const uint32_t*)(smf + (ks & 1) * STAGE_F);
        const uint32_t* Al = Ah + ARR_F;
        const uint32_t* Bh = Al + ARR_F;
        const uint32_t* Bl = Bh + ARR_F;

        #pragma unroll
        for (int kk = 0; kk < 4; kk++) {
            const int r0 = kk * 8 + q;
            const int r1 = r0 + 4;
            uint32_t afh[2][4], afl[2][4], bfh[8][2], bfl[8][2];
            #pragma unroll
            for (int mf = 0; mf < 2; mf++) {
                int m = mbase + mf * 16 + g;
                afh[mf][0] = Ah[r0 * ROWP + m];
                afh[mf][1] = Ah[r0 * ROWP + m + 8];
                afh[mf][2] = Ah[r1 * ROWP + m];
                afh[mf][3] = Ah[r1 * ROWP + m + 8];
                afl[mf][0] = Al[r0 * ROWP + m];
                afl[mf][1] = Al[r0 * ROWP + m + 8];
                afl[mf][2] = Al[r1 * ROWP + m];
                afl[mf][3] = Al[r1 * ROWP + m + 8];
            }
            #pragma unroll
            for (int nf = 0; nf < 8; nf++) {
                int n = nbase + nf * 8 + g;
                bfh[nf][0] = Bh[r0 * ROWP + n];
                bfh[nf][1] = Bh[r1 * ROWP + n];
                bfl[nf][0] = Bl[r0 * ROWP + n];
                bfl[nf][1] = Bl[r1 * ROWP + n];
            }
            #pragma unroll
            for (int mf = 0; mf < 2; mf++)
                #pragma unroll
                for (int nf = 0; nf < 8; nf++) {
                    MMA_TF32(acc[mf][nf], afh[mf], bfh[nf]);  // hi*hi
                    MMA_TF32(acc[mf][nf], afh[mf], bfl[nf]);  // hi*lo
                    MMA_TF32(acc[mf][nf], afl[mf], bfh[nf]);  // lo*hi
                }
        }
        __syncthreads();
    }

    // epilogue: d = fl( fl(zn+cn) - 2*dot ), lexicographic (d, idx) min.
    // C frag: c0/c1 at row g (cols 2q, 2q+1), c2/c3 at row g+8.
    #pragma unroll
    for (int mf = 0; mf < 2; mf++) {
        #pragma unroll
        for (int h = 0; h < 2; h++) {
            int m = mbase + mf * 16 + g + h * 8;
            int token = tb * 128 + m;
            float zn = g_znorm[token];
            unsigned long long bestpk = 0xFFFFFFFFFFFFFFFFull;
            #pragma unroll
            for (int nf = 0; nf < 8; nf++) {
                #pragma unroll
                for (int p = 0; p < 2; p++) {
                    int n = nbase + nf * 8 + q * 2 + p;
                    float dot = acc[mf][nf][h * 2 + p];
                    float cn  = __ldg(&g_cbnorm[nt0 + n]);
                    float t1  = __fadd_rn(zn, cn);
                    float d   = __fsub_rn(t1, __fmul_rn(2.0f, dot));
                    unsigned int e = __float_as_uint(d);
                    e = (e & 0x80000000u) ? ~e : (e | 0x80000000u);
                    unsigned long long pk =
                        ((unsigned long long)e << 32) | (unsigned int)(nt0 + n);
                    if (pk < bestpk) bestpk = pk;
                }
            }
            atomicMin(&g_best[token], bestpk);
        }
    }
}

// ---------------- extract indices, bump counts ----------------
__global__ void post_idx(float* __restrict__ out) {
    int n = blockIdx.x * blockDim.x + threadIdx.x;
    if (n >= NTOK) return;
    unsigned long long pk = g_best[n];
    int id = (int)(pk & 0xFFFFFFFFull);
    g_idx[n] = id;
    out[OUT_IDX + n] = (float)id;
    atomicAdd(&g_counts[id], 1.0f);
}

// ---------------- quantized output + commitment loss ----------------
__global__ void quant_loss(const float* __restrict__ x,
                           const float* __restrict__ cb,
                           float* __restrict__ out) {
    __shared__ float sred[256];
    int n = blockIdx.x;
    int c = threadIdx.x;
    int id = g_idx[n];
    float qv = __ldg(cb + (size_t)id * DIM + c);
    int b = n >> 10, hw = n & 1023;
    size_t off = (size_t)b * DIM * HW + (size_t)c * HW + hw;
    float xv = x[off];
    out[OUT_Q + off] = __fadd_rn(xv, __fsub_rn(qv, xv));
    float d = __fsub_rn(qv, xv);
    sred[c] = d * d;
    __syncthreads();
    #pragma unroll
    for (int s = 128; s > 0; s >>= 1) {
        if (c < s) sred[c] += sred[c + s];
        __syncthreads();
    }
    if (c == 0) atomicAdd(&g_loss, (double)sred[0]);
}

// ---------------- dw = segment_sum(flat, idx) ----------------
__global__ void dw_kernel(const float* __restrict__ x) {
    int n = blockIdx.x * blockDim.x + threadIdx.x;
    int d = blockIdx.y;
    int b = n >> 10, hw = n & 1023;
    float v = x[(size_t)b * DIM * HW + (size_t)d * HW + hw];
    atomicAdd(&g_dw[(size_t)g_idx[n] * DIM + d], v);
}

// ---------------- EMA finalize ----------------
__global__ void final_kernel(const float* __restrict__ ema_count,
                             const float* __restrict__ ema_weight,
                             float* __restrict__ out) {
    int k = blockIdx.x;
    int c = threadIdx.x;
    float nc = ema_count[k] * 0.95f + 0.05f * g_counts[k];
    const float denom = (float)(32768.0 + 8192.0 * 1e-5);
    nc = (nc + 1e-5f) / denom * 32768.0f;
    float w = ema_weight[(size_t)k * DIM + c] * 0.95f + 0.05f * g_dw[(size_t)k * DIM + c];
    out[OUT_W  + (size_t)k * DIM + c] = w;
    out[OUT_CB + (size_t)k * DIM + c] = w / nc;
    if (c == 0) out[OUT_CNT + k] = nc;
    if (k == 0 && c == 0) {
        double mean = g_loss / (double)((size_t)NTOK * DIM);
        out[OUT_LOSS] = 0.25f * (float)mean;
    }
}

extern "C" void kernel_launch(void* const* d_in, const int* in_sizes, int n_in,
                              void* d_out, int out_size) {
    const float* x          = (const float*)d_in[0];
    const float* cb         = (const float*)d_in[1];
    const float* ema_count  = (const float*)d_in[2];
    const float* ema_weight = (const float*)d_in[3];
    float* out = (float*)d_out;

    static int smem_set = 0;
    if (!smem_set) {
        cudaFuncSetAttribute(gemm_argmin_tc,
                             cudaFuncAttributeMaxDynamicSharedMemorySize, SMEM_B);
        smem_set = 1;
    }

    init_kernel<<<(K_CODES * DIM + 255) / 256, 256>>>();
    decomp_x<<<NTOK * DIM / 256, 256>>>(x);
    decomp_cbT<<<dim3(K_CODES / 32, DIM / 32), dim3(32, 32)>>>(cb);
    znorm_kernel<<<NTOK / 256, 256>>>(x);
    cbnorm_kernel<<<(K_CODES * 32 + 255) / 256, 256>>>(cb);
    gemm_argmin_tc<<<dim3(K_CODES / 128, NTOK / 128), 256, SMEM_B>>>();
    post_idx<<<NTOK / 256, 256>>>(out);
    quant_loss<<<NTOK, 256>>>(x, cb, out);
    dw_kernel<<<dim3(NTOK / 256, DIM), 256>>>(x);
    final_kernel<<<K_CODES, DIM>>>(ema_count, ema_weight, out);
}